// round 4
// baseline (speedup 1.0000x reference)
#include <cuda_runtime.h>
#include <cuda_bf16.h>

// FeaturesLinear: out[seg] = sum_t (weight[ids[t]] * ratings[t]) + bias
// ids: int32[N], ratings: f32[N], segs: int32[N] (sorted), weight: f32[V,16],
// bias: f32[16], out: f32[batch,16].  N = 819200 (multiple of 64).

#define DIM 16
#define TPT 4   // tokens per thread; warp covers 16 * TPT = 64 tokens

// 256-bit weight gather with L2 evict_last (keep table resident in L2).
__device__ __forceinline__ void ldg_wt8(const float* p, float v[8]) {
    unsigned a0,a1,a2,a3,a4,a5,a6,a7;
    asm("ld.global.nc.L2::evict_last.v8.b32 {%0,%1,%2,%3,%4,%5,%6,%7}, [%8];"
        : "=r"(a0),"=r"(a1),"=r"(a2),"=r"(a3),
          "=r"(a4),"=r"(a5),"=r"(a6),"=r"(a7)
        : "l"(p));
    v[0]=__uint_as_float(a0); v[1]=__uint_as_float(a1);
    v[2]=__uint_as_float(a2); v[3]=__uint_as_float(a3);
    v[4]=__uint_as_float(a4); v[5]=__uint_as_float(a5);
    v[6]=__uint_as_float(a6); v[7]=__uint_as_float(a7);
}

__global__ void fl_init_out(float4* __restrict__ out,
                            const float4* __restrict__ bias4,
                            int out_quads) {
    int i = blockIdx.x * blockDim.x + threadIdx.x;
    if (i < out_quads) out[i] = __ldg(&bias4[i & 3]);
}

// Lane layout: slot = lane & 1 (which 32B half of the 64B row),
// tokGroup = lane >> 1 (0..15). Thread handles TPT consecutive tokens.
__global__ __launch_bounds__(256)
void fl_main(const int*   __restrict__ ids,
             const float* __restrict__ ratings,
             const int*   __restrict__ segs,
             const float* __restrict__ weight,
             float*       __restrict__ out,
             int n) {
    const int lane     = threadIdx.x & 31;
    const int slot     = lane & 1;
    const int tokGroup = lane >> 1;
    const int warpsPerBlock = blockDim.x >> 5;
    const int warpId   = blockIdx.x * warpsPerBlock + (threadIdx.x >> 5);

    const int base = warpId * (16 * TPT) + tokGroup * TPT;
    if (base >= n) return;

    // ---- metadata for 4 tokens (streaming loads; don't pollute L2)
    int4   idv = __ldcs((const int4*)  (ids     + base));
    float4 rv  = __ldcs((const float4*)(ratings + base));
    int4   sv  = __ldcs((const int4*)  (segs    + base));

    const int   id[TPT] = {idv.x, idv.y, idv.z, idv.w};
    const float r [TPT] = {rv.x,  rv.y,  rv.z,  rv.w};
    const int   sg[TPT] = {sv.x,  sv.y,  sv.z,  sv.w};

    // ---- issue all 4 independent 32B half-row gathers up front
    float w[TPT][8];
    #pragma unroll
    for (int k = 0; k < TPT; k++)
        ldg_wt8(weight + (size_t)id[k] * DIM + slot * 8, w[k]);

    // ---- thread-serial accumulation with flush on segment boundary
    float acc[8];
    #pragma unroll
    for (int j = 0; j < 8; j++) acc[j] = w[0][j] * r[0];

    #pragma unroll
    for (int k = 1; k < TPT; k++) {
        if (sg[k] != sg[k - 1]) {
            float* o = out + (size_t)sg[k - 1] * DIM + slot * 8;
            #pragma unroll
            for (int j = 0; j < 8; j++) atomicAdd(o + j, acc[j]);
            #pragma unroll
            for (int j = 0; j < 8; j++) acc[j] = 0.f;
        }
        #pragma unroll
        for (int j = 0; j < 8; j++) acc[j] += w[k][j] * r[k];
    }

    // ---- cross-lane segmented suffix reduction on trailing partials.
    // Trailing keys are monotone across the warp (sorted segs), so the
    // strided conditional add is an exact segmented reduction.
    int seg = sg[TPT - 1];
    #pragma unroll
    for (int off = 2; off <= 16; off <<= 1) {
        int oseg = __shfl_down_sync(0xffffffffu, seg, off);
        float ov[8];
        #pragma unroll
        for (int j = 0; j < 8; j++)
            ov[j] = __shfl_down_sync(0xffffffffu, acc[j], off);
        if ((lane + off) < 32 && oseg == seg) {
            #pragma unroll
            for (int j = 0; j < 8; j++) acc[j] += ov[j];
        }
    }

    const int  pseg = __shfl_up_sync(0xffffffffu, seg, 2);
    const bool head = (tokGroup == 0) || (pseg != seg);

    if (head) {
        float* o = out + (size_t)seg * DIM + slot * 8;
        #pragma unroll
        for (int j = 0; j < 8; j++) atomicAdd(o + j, acc[j]);
    }
}

extern "C" void kernel_launch(void* const* d_in, const int* in_sizes, int n_in,
                              void* d_out, int out_size) {
    const int*   ids     = (const int*)  d_in[0];
    const float* ratings = (const float*)d_in[1];
    const int*   segs    = (const int*)  d_in[2];
    // d_in[3] = batch_size scalar (unused)
    const float* weight  = (const float*)d_in[4];
    const float* bias    = (const float*)d_in[5];
    float*       out     = (float*)d_out;

    const int n = in_sizes[0];

    // Init output with bias (vectorized).
    {
        int quads   = out_size / 4;
        int threads = 256;
        int blocks  = (quads + threads - 1) / threads;
        fl_init_out<<<blocks, threads>>>((float4*)out, (const float4*)bias, quads);
    }

    // Main gather + segmented reduce: 64 tokens per warp, 8 warps per block.
    {
        int warps   = (n + 16 * TPT - 1) / (16 * TPT);
        int threads = 256;
        int blocks  = (warps + 7) / 8;
        fl_main<<<blocks, threads>>>(ids, ratings, segs, weight, out, n);
    }
}